// round 16
// baseline (speedup 1.0000x reference)
#include <cuda_runtime.h>
#include <cuda_fp16.h>
#include <math.h>

#define GS 480
#define IMS 384
#define NCH 16
#define KPTS 500000
#define PAD 48
#define HALF 240
#define NT 256
#define GPTS 256                 // gather points per block
#define CH_STR 1032              // float stride per chunk in gather staging (4*256 + 8)
#define HPLANE (GS * GS * 8)     // __half2 elements per half-channel plane

// Scratch (allocation-free: __device__ globals), both fp16 -> L2-resident
__device__ __align__(16) __half2 g_buf1[NCH * GS * GS];  // [c][ky][x] after pass 1
__device__ __align__(16) __half2 g_buf2[2 * HPLANE];     // [h][kx][ky][c8] after pass 2

__device__ __forceinline__ float2 cmulf(float2 a, float2 b) {
    return make_float2(a.x * b.x - a.y * b.y, a.x * b.y + a.y * b.x);
}
__device__ __forceinline__ float2 cadd(float2 a, float2 b) { return make_float2(a.x + b.x, a.y + b.y); }
__device__ __forceinline__ float2 csub(float2 a, float2 b) { return make_float2(a.x - b.x, a.y - b.y); }

// forward DFT-3 (w = exp(-2pi i/3))
__device__ __forceinline__ void dft3(float2 x0, float2 x1, float2 x2,
                                     float2& X0, float2& X1, float2& X2)
{
    const float c = -0.5f, s = -0.86602540378443865f;
    float2 t = cadd(x1, x2);
    float2 d = csub(x1, x2);
    X0 = cadd(x0, t);
    float2 m = make_float2(fmaf(c, t.x, x0.x), fmaf(c, t.y, x0.y));
    float2 e = make_float2(-s * d.y, s * d.x);     // i*s*d
    X1 = cadd(m, e);
    X2 = csub(m, e);
}

// forward DFT-5 (w = exp(-2pi i/5))
__device__ __forceinline__ void dft5(float2 x0, float2 x1, float2 x2, float2 x3, float2 x4,
                                     float2& X0, float2& X1, float2& X2, float2& X3, float2& X4)
{
    const float c1 = 0.30901699437494742f, c2 = -0.80901699437494745f;
    const float s1 = 0.95105651629515353f, s2 =  0.58778525229247314f;
    float2 t1 = cadd(x1, x4), t2 = cadd(x2, x3);
    float2 t3 = csub(x1, x4), t4 = csub(x2, x3);
    X0 = cadd(x0, cadd(t1, t2));
    float2 m1 = make_float2(fmaf(c1, t1.x, fmaf(c2, t2.x, x0.x)),
                            fmaf(c1, t1.y, fmaf(c2, t2.y, x0.y)));
    float2 m2 = make_float2(fmaf(c2, t1.x, fmaf(c1, t2.x, x0.x)),
                            fmaf(c2, t1.y, fmaf(c1, t2.y, x0.y)));
    float2 u1 = make_float2(fmaf(s1, t3.x,  s2 * t4.x), fmaf(s1, t3.y,  s2 * t4.y));
    float2 u2 = make_float2(fmaf(s2, t3.x, -s1 * t4.x), fmaf(s2, t3.y, -s1 * t4.y));
    X1 = make_float2(m1.x + u1.y, m1.y - u1.x);    // m1 - i*u1
    X4 = make_float2(m1.x - u1.y, m1.y + u1.x);    // m1 + i*u1
    X2 = make_float2(m2.x + u2.y, m2.y - u2.x);    // m2 - i*u2
    X3 = make_float2(m2.x - u2.y, m2.y + u2.x);    // m2 + i*u2
}

// Full 15-point DFT over n2 via PFA (15 = 3*5, CRT maps, no inter-twiddles).
// Inputs xv[j] = x[n2] with n2 = j (j<6) or j+3 (j>=6); n2 in {6,7,8} are zero.
__device__ __forceinline__ void dft15_pfa(const float2 xv[12], float2 A[15])
{
    const float2 Z = make_float2(0.f, 0.f);
    float2 y0[5], y1[5], y2[5];                    // y[ka][b]
    // input map n = (5a + 3b) mod 15
    dft3(xv[0], xv[5], xv[7],  y0[0], y1[0], y2[0]);   // b=0: n=0,5,10
    dft3(xv[3], Z,     xv[10], y0[1], y1[1], y2[1]);   // b=1: n=3,(8),13
    dft3(Z,     xv[8], xv[1],  y0[2], y1[2], y2[2]);   // b=2: n=(6),11,1
    dft3(xv[6], xv[11],xv[4],  y0[3], y1[3], y2[3]);   // b=3: n=9,14,4
    dft3(xv[9], xv[2], Z,      y0[4], y1[4], y2[4]);   // b=4: n=12,2,(7)
    // output map k = (10*ka + 6*kb) mod 15
    dft5(y0[0], y0[1], y0[2], y0[3], y0[4], A[0],  A[6],  A[12], A[3],  A[9]);
    dft5(y1[0], y1[1], y1[2], y1[3], y1[4], A[10], A[1],  A[7],  A[13], A[4]);
    dft5(y2[0], y2[1], y2[2], y2[3], y2[4], A[5],  A[11], A[2],  A[8],  A[14]);
}

// Per-lane butterfly constants (uniform, non-predicated).
struct BT {
    float2 t16, t8, t4, t2, base;
    float g16, g8, g4, g2, g1;
};

__device__ __forceinline__ float2 shfl2(float2 v, int src) {
    return make_float2(__shfl_sync(0xffffffffu, v.x, src),
                       __shfl_sync(0xffffffffu, v.y, src));
}

// One sincospif builds a(lane) = exp(-i*pi*(lane&15)/16); all four stage
// twiddles are lane-indexed samples of it.
__device__ __forceinline__ BT make_bt(int lane) {
    BT bt; float s, c;
    sincospif(-(float)(lane & 15) * (1.0f / 16.0f), &s, &c);
    float2 a = make_float2(c, s);
    int s16 = (lane & 16) ? (lane & 15) : 0;
    int s8  = (lane &  8) ? 2 * (lane & 7) : 0;
    int s4  = (lane &  4) ? 4 * (lane & 3) : 0;
    int s2  = (lane &  2) ? 8 * (lane & 1) : 0;
    bt.t16 = shfl2(a, s16);
    bt.t8  = shfl2(a, s8);
    bt.t4  = shfl2(a, s4);
    bt.t2  = shfl2(a, s2);
    sincospif(-(float)lane * (1.0f / 240.0f), &s, &c); bt.base = make_float2(c, s);  // w480^lane
    bt.g16 = (lane & 16) ? -1.f : 1.f;
    bt.g8  = (lane &  8) ? -1.f : 1.f;
    bt.g4  = (lane &  4) ? -1.f : 1.f;
    bt.g2  = (lane &  2) ? -1.f : 1.f;
    bt.g1  = (lane &  1) ? -1.f : 1.f;
    return bt;
}

template<int H>
__device__ __forceinline__ void bfly_u(float2& v, float2 twf, float sgn) {
    float ox = __shfl_xor_sync(0xffffffffu, v.x, H);
    float oy = __shfl_xor_sync(0xffffffffu, v.y, H);
    v = cmulf(make_float2(fmaf(sgn, v.x, ox), fmaf(sgn, v.y, oy)), twf);
}

// 32-pt FFT across lanes (input pre-twiddled). Output bit-reversed over lanes.
__device__ __forceinline__ float2 fft32_lanes(float2 v, const BT& bt)
{
    bfly_u<16>(v, bt.t16, bt.g16);
    bfly_u<8> (v, bt.t8,  bt.g8);
    bfly_u<4> (v, bt.t4,  bt.g4);
    bfly_u<2> (v, bt.t2,  bt.g2);
    float ox = __shfl_xor_sync(0xffffffffu, v.x, 1);
    float oy = __shfl_xor_sync(0xffffffffu, v.y, 1);
    return make_float2(fmaf(bt.g1, v.x, ox), fmaf(bt.g1, v.y, oy));
}

// Pass 1: FFT along Y for the 384 nonzero x-rows. One warp per row.
// Writes fp16 buf1[c][ky][x] via shared staging (coalesced 32B runs).
__global__ __launch_bounds__(NT) void pass1_kernel(
    const float* __restrict__ img_re, const float* __restrict__ img_im)
{
    __shared__ __half2 sh2[GS * 9];    // [ky][8 rows], stride 9

    const int t = threadIdx.x, lane = t & 31, w = t >> 5;
    const int b = blockIdx.x;
    const int c = b / 48;
    const int g = b - c * 48;
    int x0 = g * 8; if (x0 >= 192) x0 += 96;       // valid x: [0,192) U [288,480)

    const int x = x0 + w;
    int px = x + HALF; if (px >= GS) px -= GS;
    const int ix = px - PAD;                        // in [0,384)
    const float* rre = img_re + (c * IMS + ix) * IMS;
    const float* rim = img_im + (c * IMS + ix) * IMS;

    float2 xv[12];
    #pragma unroll
    for (int j = 0; j < 12; j++) {
        int n2 = (j < 6) ? j : j + 3;
        int n = lane + 32 * n2;
        int py = n + HALF; if (py >= GS) py -= GS;
        int iy = py - PAD;                          // in [0,384)
        xv[j].x = rre[iy];
        xv[j].y = rim[iy];
    }

    float2 A[15];
    dft15_pfa(xv, A);

    const BT bt = make_bt(lane);
    const int k1 = (int)(__brev((unsigned)lane) >> 27);
    float2 tw = make_float2(1.f, 0.f);
    #pragma unroll
    for (int k2 = 0; k2 < 15; k2++) {
        float2 v = fft32_lanes(cmulf(A[k2], tw), bt);
        sh2[(15 * k1 + k2) * 9 + w] = __float22half2_rn(v);
        tw = cmulf(tw, bt.base);
    }
    __syncthreads();

    #pragma unroll
    for (int idx = t; idx < GS * 8; idx += NT) {
        int ky = idx >> 3, j = idx & 7;
        g_buf1[(c * GS + ky) * GS + x0 + j] = sh2[ky * 9 + j];
    }
}

// Pass 2: FFT along X. Block = (ky, half); 8 warps = 8 channels of one ky row.
// Loads fp16 buf1, stages fp16, writes buf2[h][kx][ky][c8] as dense 32B runs.
__global__ __launch_bounds__(NT) void pass2_kernel()
{
    __shared__ __half2 sh2[GS * 9];    // [kx][8 channels], stride 9

    const int t = threadIdx.x, lane = t & 31, w = t >> 5;
    const int b = blockIdx.x;
    const int ky = b >> 1;
    const int h  = b & 1;
    const int c  = h * 8 + w;

    const __half2* src = g_buf1 + (c * GS + ky) * GS;
    float2 xv[12];
    #pragma unroll
    for (int j = 0; j < 12; j++) {
        int n2 = (j < 6) ? j : j + 3;
        xv[j] = __half22float2(src[lane + 32 * n2]);  // coalesced 128B per n2
    }

    float2 A[15];
    dft15_pfa(xv, A);

    const BT bt = make_bt(lane);
    const int k1 = (int)(__brev((unsigned)lane) >> 27);
    float2 tw = make_float2(1.0f / 480.0f, 0.f);    // ortho norm seed
    #pragma unroll
    for (int k2 = 0; k2 < 15; k2++) {
        float2 v = fft32_lanes(cmulf(A[k2], tw), bt);
        sh2[(15 * k1 + k2) * 9 + w] = __float22half2_rn(v);
        tw = cmulf(tw, bt.base);
    }
    __syncthreads();

    __half2* dst = g_buf2 + h * HPLANE + ky * 8;    // [kx][ky][c8]
    #pragma unroll
    for (int idx = t; idx < GS * 8; idx += NT) {
        int kx = idx >> 3, lc = idx & 7;
        dst[kx * (GS * 8) + lc] = sh2[kx * 9 + lc]; // 32B runs per kx
    }
}

// Gather v7: fp16 buf2, 256 points/block. Index math once (A); 4 lanes/point
// 16B loads with half->float convert into SoA staging (B); conflict-free
// LDS.128 reads of 4 consecutive points + direct STG.128 (C).
__global__ __launch_bounds__(256) void gather_kernel(
    const float* __restrict__ trj, float* __restrict__ out)
{
    __shared__ float sh[8 * CH_STR];   // 33 KB
    __shared__ int   su[GPTS];

    const int t = threadIdx.x;
    const int base = blockIdx.x * GPTS;

    // Phase A: one thread per point computes the plane offset (in __half2 units).
    {
        int kp = base + t;
        int kc = (kp < KPTS) ? kp : (KPTS - 1);
        float2 tt = *reinterpret_cast<const float2*>(trj + 2 * kc);
        float fx = __fadd_rn(__fmul_rn(tt.x, 1.25f), 240.0f);
        float fy = __fadd_rn(__fmul_rn(tt.y, 1.25f), 240.0f);
        fx = fminf(fmaxf(fx, 0.0f), 479.0f);
        fy = fminf(fmaxf(fy, 0.0f), 479.0f);
        int ixg = (int)rintf(fx);
        int iyg = (int)rintf(fy);
        int ux = ixg + HALF; if (ux >= GS) ux -= GS;
        int uy = iyg + HALF; if (uy >= GS) uy -= GS;
        su[t] = (ux * GS + uy) * 8;
    }
    __syncthreads();

    // Phase B: 4 chunks/point (q = h*2 + j), 16B each = 4 channels (re,im) fp16.
    // Convert to fp32 into staging layout sh[q8][comp][point].
    #pragma unroll
    for (int it = 0; it < GPTS / 64; it++) {
        int pl = it * 64 + (t >> 2);
        int q  = t & 3;
        int u  = su[pl];
        int h = q >> 1, j = q & 1;
        const uint4* p4 = reinterpret_cast<const uint4*>(g_buf2 + h * HPLANE + u);
        uint4 v = p4[j];
        unsigned int vm[4] = {v.x, v.y, v.z, v.w};
        #pragma unroll
        for (int m = 0; m < 4; m++) {
            __half2 hm = *reinterpret_cast<__half2*>(&vm[m]);
            float2 f = __half22float2(hm);          // (re, im) of channel h*8+j*4+m
            int q8 = 2 * q + (m >> 1);              // = h*4 + (c8>>1), c8 = j*4+m
            float* dq = sh + q8 * CH_STR + ((m & 1) << 1) * GPTS + pl;
            dq[0]    = f.x;                         // comp = (c8&1)*2 + 0 (re)
            dq[GPTS] = f.y;                         // comp = (c8&1)*2 + 1 (im)
        }
    }
    __syncthreads();

    // Phase C: 32 output rows x GPTS points; LDS.128 conflict-free + STG.128.
    #pragma unroll
    for (int it2 = 0; it2 < GPTS / 32; it2++) {
        int task = t + it2 * 256;                   // 32 rows x (GPTS/4) groups
        int oc = task / (GPTS / 4);
        int l  = task & (GPTS / 4 - 1);
        int k  = base + 4 * l;
        if (k < KPTS) {                             // KPTS % 4 == 0
            int reim = oc >> 4;
            int c    = oc & 15;
            int h    = c >> 3, c8 = c & 7;
            int q    = h * 4 + (c8 >> 1);
            int comp = ((c8 & 1) << 1) + reim;
            float4 v = *reinterpret_cast<const float4*>(sh + q * CH_STR + comp * GPTS + 4 * l);
            *reinterpret_cast<float4*>(out + oc * KPTS + k) = v;
        }
    }
}

extern "C" void kernel_launch(void* const* d_in, const int* in_sizes, int n_in,
                              void* d_out, int out_size)
{
    const float* img_re = (const float*)d_in[0];   // (1,16,384,384)
    const float* img_im = (const float*)d_in[1];   // (1,16,384,384)
    const float* trj    = (const float*)d_in[2];   // (1,500000,2)
    float* out = (float*)d_out;                    // (2,1,16,500000)

    pass1_kernel<<<NCH * 48, NT>>>(img_re, img_im);
    pass2_kernel<<<GS * 2, NT>>>();
    gather_kernel<<<(KPTS + GPTS - 1) / GPTS, 256>>>(trj, out);
}

// round 17
// speedup vs baseline: 1.1346x; 1.1346x over previous
#include <cuda_runtime.h>
#include <cuda_fp16.h>
#include <math.h>

#define GS 480
#define IMS 384
#define NCH 16
#define KPTS 500000
#define PAD 48
#define HALF 240
#define NT 256
#define GPTS 128                 // gather points per block
#define CH_STR 520               // float stride per chunk in gather staging
#define HPLANE (GS * GS * 8)     // __half2 elements per half-channel plane

// Scratch (allocation-free: __device__ globals), both fp16 -> L2-resident
__device__ __align__(16) __half2 g_buf1[NCH * GS * GS];  // [c][ky][x] after pass 1
__device__ __align__(16) __half2 g_buf2[2 * HPLANE];     // [h][kx][ky][c8] after pass 2

__device__ __forceinline__ float2 cmulf(float2 a, float2 b) {
    return make_float2(a.x * b.x - a.y * b.y, a.x * b.y + a.y * b.x);
}
__device__ __forceinline__ float2 cadd(float2 a, float2 b) { return make_float2(a.x + b.x, a.y + b.y); }
__device__ __forceinline__ float2 csub(float2 a, float2 b) { return make_float2(a.x - b.x, a.y - b.y); }

// forward DFT-3 (w = exp(-2pi i/3))
__device__ __forceinline__ void dft3(float2 x0, float2 x1, float2 x2,
                                     float2& X0, float2& X1, float2& X2)
{
    const float c = -0.5f, s = -0.86602540378443865f;
    float2 t = cadd(x1, x2);
    float2 d = csub(x1, x2);
    X0 = cadd(x0, t);
    float2 m = make_float2(fmaf(c, t.x, x0.x), fmaf(c, t.y, x0.y));
    float2 e = make_float2(-s * d.y, s * d.x);     // i*s*d
    X1 = cadd(m, e);
    X2 = csub(m, e);
}

// forward DFT-5 (w = exp(-2pi i/5))
__device__ __forceinline__ void dft5(float2 x0, float2 x1, float2 x2, float2 x3, float2 x4,
                                     float2& X0, float2& X1, float2& X2, float2& X3, float2& X4)
{
    const float c1 = 0.30901699437494742f, c2 = -0.80901699437494745f;
    const float s1 = 0.95105651629515353f, s2 =  0.58778525229247314f;
    float2 t1 = cadd(x1, x4), t2 = cadd(x2, x3);
    float2 t3 = csub(x1, x4), t4 = csub(x2, x3);
    X0 = cadd(x0, cadd(t1, t2));
    float2 m1 = make_float2(fmaf(c1, t1.x, fmaf(c2, t2.x, x0.x)),
                            fmaf(c1, t1.y, fmaf(c2, t2.y, x0.y)));
    float2 m2 = make_float2(fmaf(c2, t1.x, fmaf(c1, t2.x, x0.x)),
                            fmaf(c2, t1.y, fmaf(c1, t2.y, x0.y)));
    float2 u1 = make_float2(fmaf(s1, t3.x,  s2 * t4.x), fmaf(s1, t3.y,  s2 * t4.y));
    float2 u2 = make_float2(fmaf(s2, t3.x, -s1 * t4.x), fmaf(s2, t3.y, -s1 * t4.y));
    X1 = make_float2(m1.x + u1.y, m1.y - u1.x);    // m1 - i*u1
    X4 = make_float2(m1.x - u1.y, m1.y + u1.x);    // m1 + i*u1
    X2 = make_float2(m2.x + u2.y, m2.y - u2.x);    // m2 - i*u2
    X3 = make_float2(m2.x - u2.y, m2.y + u2.x);    // m2 + i*u2
}

// Full 15-point DFT over n2 via PFA (15 = 3*5, CRT maps, no inter-twiddles).
// Inputs xv[j] = x[n2] with n2 = j (j<6) or j+3 (j>=6); n2 in {6,7,8} are zero.
__device__ __forceinline__ void dft15_pfa(const float2 xv[12], float2 A[15])
{
    const float2 Z = make_float2(0.f, 0.f);
    float2 y0[5], y1[5], y2[5];                    // y[ka][b]
    // input map n = (5a + 3b) mod 15
    dft3(xv[0], xv[5], xv[7],  y0[0], y1[0], y2[0]);   // b=0: n=0,5,10
    dft3(xv[3], Z,     xv[10], y0[1], y1[1], y2[1]);   // b=1: n=3,(8),13
    dft3(Z,     xv[8], xv[1],  y0[2], y1[2], y2[2]);   // b=2: n=(6),11,1
    dft3(xv[6], xv[11],xv[4],  y0[3], y1[3], y2[3]);   // b=3: n=9,14,4
    dft3(xv[9], xv[2], Z,      y0[4], y1[4], y2[4]);   // b=4: n=12,2,(7)
    // output map k = (10*ka + 6*kb) mod 15
    dft5(y0[0], y0[1], y0[2], y0[3], y0[4], A[0],  A[6],  A[12], A[3],  A[9]);
    dft5(y1[0], y1[1], y1[2], y1[3], y1[4], A[10], A[1],  A[7],  A[13], A[4]);
    dft5(y2[0], y2[1], y2[2], y2[3], y2[4], A[5],  A[11], A[2],  A[8],  A[14]);
}

// Per-lane butterfly constants (uniform, non-predicated).
struct BT {
    float2 t16, t8, t4, t2, base;
    float g16, g8, g4, g2, g1;
};

__device__ __forceinline__ float2 shfl2(float2 v, int src) {
    return make_float2(__shfl_sync(0xffffffffu, v.x, src),
                       __shfl_sync(0xffffffffu, v.y, src));
}

// One sincospif builds a(lane) = exp(-i*pi*(lane&15)/16); all four stage
// twiddles are lane-indexed samples of it.
__device__ __forceinline__ BT make_bt(int lane) {
    BT bt; float s, c;
    sincospif(-(float)(lane & 15) * (1.0f / 16.0f), &s, &c);
    float2 a = make_float2(c, s);
    int s16 = (lane & 16) ? (lane & 15) : 0;
    int s8  = (lane &  8) ? 2 * (lane & 7) : 0;
    int s4  = (lane &  4) ? 4 * (lane & 3) : 0;
    int s2  = (lane &  2) ? 8 * (lane & 1) : 0;
    bt.t16 = shfl2(a, s16);
    bt.t8  = shfl2(a, s8);
    bt.t4  = shfl2(a, s4);
    bt.t2  = shfl2(a, s2);
    sincospif(-(float)lane * (1.0f / 240.0f), &s, &c); bt.base = make_float2(c, s);  // w480^lane
    bt.g16 = (lane & 16) ? -1.f : 1.f;
    bt.g8  = (lane &  8) ? -1.f : 1.f;
    bt.g4  = (lane &  4) ? -1.f : 1.f;
    bt.g2  = (lane &  2) ? -1.f : 1.f;
    bt.g1  = (lane &  1) ? -1.f : 1.f;
    return bt;
}

template<int H>
__device__ __forceinline__ void bfly_u(float2& v, float2 twf, float sgn) {
    float ox = __shfl_xor_sync(0xffffffffu, v.x, H);
    float oy = __shfl_xor_sync(0xffffffffu, v.y, H);
    v = cmulf(make_float2(fmaf(sgn, v.x, ox), fmaf(sgn, v.y, oy)), twf);
}

// 32-pt FFT across lanes (input pre-twiddled). Output bit-reversed over lanes.
__device__ __forceinline__ float2 fft32_lanes(float2 v, const BT& bt)
{
    bfly_u<16>(v, bt.t16, bt.g16);
    bfly_u<8> (v, bt.t8,  bt.g8);
    bfly_u<4> (v, bt.t4,  bt.g4);
    bfly_u<2> (v, bt.t2,  bt.g2);
    float ox = __shfl_xor_sync(0xffffffffu, v.x, 1);
    float oy = __shfl_xor_sync(0xffffffffu, v.y, 1);
    return make_float2(fmaf(bt.g1, v.x, ox), fmaf(bt.g1, v.y, oy));
}

// Pass 1: FFT along Y for the 384 nonzero x-rows. One warp per row.
// Writes fp16 buf1[c][ky][x] via shared staging (coalesced 32B runs).
__global__ __launch_bounds__(NT) void pass1_kernel(
    const float* __restrict__ img_re, const float* __restrict__ img_im)
{
    __shared__ __half2 sh2[GS * 9];    // [ky][8 rows], stride 9

    const int t = threadIdx.x, lane = t & 31, w = t >> 5;
    const int b = blockIdx.x;
    const int c = b / 48;
    const int g = b - c * 48;
    int x0 = g * 8; if (x0 >= 192) x0 += 96;       // valid x: [0,192) U [288,480)

    const int x = x0 + w;
    int px = x + HALF; if (px >= GS) px -= GS;
    const int ix = px - PAD;                        // in [0,384)
    const float* rre = img_re + (c * IMS + ix) * IMS;
    const float* rim = img_im + (c * IMS + ix) * IMS;

    float2 xv[12];
    #pragma unroll
    for (int j = 0; j < 12; j++) {
        int n2 = (j < 6) ? j : j + 3;
        int n = lane + 32 * n2;
        int py = n + HALF; if (py >= GS) py -= GS;
        int iy = py - PAD;                          // in [0,384)
        xv[j].x = rre[iy];
        xv[j].y = rim[iy];
    }

    float2 A[15];
    dft15_pfa(xv, A);

    const BT bt = make_bt(lane);
    const int k1 = (int)(__brev((unsigned)lane) >> 27);
    float2 tw = make_float2(1.f, 0.f);
    #pragma unroll
    for (int k2 = 0; k2 < 15; k2++) {
        float2 v = fft32_lanes(cmulf(A[k2], tw), bt);
        sh2[(15 * k1 + k2) * 9 + w] = __float22half2_rn(v);
        tw = cmulf(tw, bt.base);
    }
    __syncthreads();

    #pragma unroll
    for (int idx = t; idx < GS * 8; idx += NT) {
        int ky = idx >> 3, j = idx & 7;
        g_buf1[(c * GS + ky) * GS + x0 + j] = sh2[ky * 9 + j];
    }
}

// Pass 2: FFT along X. Block = (ky, half); 8 warps = 8 channels of one ky row.
// Loads fp16 buf1, stages fp16, writes buf2[h][kx][ky][c8] as dense 32B runs.
__global__ __launch_bounds__(NT) void pass2_kernel()
{
    __shared__ __half2 sh2[GS * 9];    // [kx][8 channels], stride 9

    const int t = threadIdx.x, lane = t & 31, w = t >> 5;
    const int b = blockIdx.x;
    const int ky = b >> 1;
    const int h  = b & 1;
    const int c  = h * 8 + w;

    const __half2* src = g_buf1 + (c * GS + ky) * GS;
    float2 xv[12];
    #pragma unroll
    for (int j = 0; j < 12; j++) {
        int n2 = (j < 6) ? j : j + 3;
        xv[j] = __half22float2(src[lane + 32 * n2]);  // coalesced 128B per n2
    }

    float2 A[15];
    dft15_pfa(xv, A);

    const BT bt = make_bt(lane);
    const int k1 = (int)(__brev((unsigned)lane) >> 27);
    float2 tw = make_float2(1.0f / 480.0f, 0.f);    // ortho norm seed
    #pragma unroll
    for (int k2 = 0; k2 < 15; k2++) {
        float2 v = fft32_lanes(cmulf(A[k2], tw), bt);
        sh2[(15 * k1 + k2) * 9 + w] = __float22half2_rn(v);
        tw = cmulf(tw, bt.base);
    }
    __syncthreads();

    __half2* dst = g_buf2 + h * HPLANE + ky * 8;    // [kx][ky][c8]
    #pragma unroll
    for (int idx = t; idx < GS * 8; idx += NT) {
        int kx = idx >> 3, lc = idx & 7;
        dst[kx * (GS * 8) + lc] = sh2[kx * 9 + lc]; // 32B runs per kx
    }
}

// Gather v6 + streaming output stores: fp16 buf2, GPTS=128. Index math once
// (A); 4 lanes/point 16B loads with half->float convert into SoA staging (B);
// conflict-free LDS.128 reads + __stcs STG.128 (C) so the 64MB output stream
// doesn't evict the L2-resident fp16 buffers.
__global__ __launch_bounds__(256) void gather_kernel(
    const float* __restrict__ trj, float* __restrict__ out)
{
    __shared__ float sh[8 * CH_STR];   // 16.6 KB
    __shared__ int   su[GPTS];

    const int t = threadIdx.x;
    const int base = blockIdx.x * GPTS;

    // Phase A: one thread per point computes the plane offset (in __half2 units).
    if (t < GPTS) {
        int kp = base + t;
        int kc = (kp < KPTS) ? kp : (KPTS - 1);
        float2 tt = *reinterpret_cast<const float2*>(trj + 2 * kc);
        float fx = __fadd_rn(__fmul_rn(tt.x, 1.25f), 240.0f);
        float fy = __fadd_rn(__fmul_rn(tt.y, 1.25f), 240.0f);
        fx = fminf(fmaxf(fx, 0.0f), 479.0f);
        fy = fminf(fmaxf(fy, 0.0f), 479.0f);
        int ixg = (int)rintf(fx);
        int iyg = (int)rintf(fy);
        int ux = ixg + HALF; if (ux >= GS) ux -= GS;
        int uy = iyg + HALF; if (uy >= GS) uy -= GS;
        su[t] = (ux * GS + uy) * 8;
    }
    __syncthreads();

    // Phase B: 4 chunks/point (q = h*2 + j), 16B each = 4 channels (re,im) fp16.
    // Convert to fp32 into staging layout sh[q8][comp][point].
    #pragma unroll
    for (int it = 0; it < GPTS / 64; it++) {
        int pl = it * 64 + (t >> 2);
        int q  = t & 3;
        int u  = su[pl];
        int h = q >> 1, j = q & 1;
        const uint4* p4 = reinterpret_cast<const uint4*>(g_buf2 + h * HPLANE + u);
        uint4 v = p4[j];
        unsigned int vm[4] = {v.x, v.y, v.z, v.w};
        #pragma unroll
        for (int m = 0; m < 4; m++) {
            __half2 hm = *reinterpret_cast<__half2*>(&vm[m]);
            float2 f = __half22float2(hm);          // (re, im) of channel h*8+j*4+m
            int q8 = 2 * q + (m >> 1);              // = h*4 + (c8>>1), c8 = j*4+m
            float* dq = sh + q8 * CH_STR + ((m & 1) << 1) * 128 + pl;
            dq[0]   = f.x;                          // comp = (c8&1)*2 + 0 (re)
            dq[128] = f.y;                          // comp = (c8&1)*2 + 1 (im)
        }
    }
    __syncthreads();

    // Phase C: 32 output rows x GPTS points; LDS.128 conflict-free + STG.128.CS.
    #pragma unroll
    for (int it2 = 0; it2 < GPTS / 32; it2++) {
        int task = t + it2 * 256;
        int oc = task >> 5;
        int l  = task & 31;
        int k  = base + 4 * l;
        if (k < KPTS) {                             // KPTS % 4 == 0
            int reim = oc >> 4;
            int c    = oc & 15;
            int h    = c >> 3, c8 = c & 7;
            int q    = h * 4 + (c8 >> 1);
            int comp = ((c8 & 1) << 1) + reim;
            float4 v = *reinterpret_cast<const float4*>(sh + q * CH_STR + comp * 128 + 4 * l);
            __stcs(reinterpret_cast<float4*>(out + oc * KPTS + k), v);
        }
    }
}

extern "C" void kernel_launch(void* const* d_in, const int* in_sizes, int n_in,
                              void* d_out, int out_size)
{
    const float* img_re = (const float*)d_in[0];   // (1,16,384,384)
    const float* img_im = (const float*)d_in[1];   // (1,16,384,384)
    const float* trj    = (const float*)d_in[2];   // (1,500000,2)
    float* out = (float*)d_out;                    // (2,1,16,500000)

    pass1_kernel<<<NCH * 48, NT>>>(img_re, img_im);
    pass2_kernel<<<GS * 2, NT>>>();
    gather_kernel<<<(KPTS + GPTS - 1) / GPTS, 256>>>(trj, out);
}